// round 1
// baseline (speedup 1.0000x reference)
#include <cuda_runtime.h>

#define NN 4096
#define TT 3
#define DD 20
#define EE 131072      // 2^17
#define ATT_DIM 128
#define HEADS 2
#define LAYERS 2
#define WPR 128        // 32-bit words per bitmap row (4096/32)
#define NEG 0.2f

// ---- device scratch (static, allocation-free) ----
__device__ unsigned g_bm[TT][NN * WPR];   // 3 x 2MB adjacency bitmaps
__device__ float    g_s0[NN];
__device__ float    g_s1[NN];
__device__ float    g_S;                  // sum of current scores
__device__ float    g_a[LAYERS][HEADS];
__device__ float    g_bb[LAYERS][HEADS];
__device__ float    g_lut[LAYERS][HEADS][8];  // B value per 3-bit type mask

// ---------------------------------------------------------------- zero bitmaps
__global__ void k_zero() {
    // 3*4096*128 words = 1,572,864 = 393,216 uint4; grid 1536x256 covers exactly
    uint4* p = reinterpret_cast<uint4*>(&g_bm[0][0]);
    int i = blockIdx.x * blockDim.x + threadIdx.x;
    p[i] = make_uint4(0u, 0u, 0u, 0u);
}

// ------------------------------------------------------- per-(layer,head) consts
__global__ void k_consts(const float* __restrict__ edge_emb,
                         const float* __restrict__ att_w) {
    int id = threadIdx.x;
    if (id < LAYERS * HEADS) {
        int l = id / HEADS, h = id % HEADS;
        const float* w = att_w + (l * HEADS + h) * (DD + 2);
        float et[TT];
        for (int t = 0; t < TT; t++) {
            float acc = 0.0f;
            for (int d = 0; d < DD; d++) acc += edge_emb[t * DD + d] * w[1 + d];
            et[t] = acc;
        }
        g_a[l][h]  = w[0];
        g_bb[l][h] = w[DD + 1];
        for (int m = 0; m < 8; m++) {
            float B = 0.0f;
            for (int t = 0; t < TT; t++) if ((m >> t) & 1) B += et[t];
            g_lut[l][h][m] = B;
        }
    }
}

// ---------------------------------------------------------------- edge scatter
__global__ void k_scatter(const int* __restrict__ el) {
    int i = blockIdx.x * blockDim.x + threadIdx.x;   // i < TT*EE
    int t = i >> 17;               // EE = 2^17
    int e = i & (EE - 1);
    int s = el[(t * 2 + 0) * EE + e];
    int g = el[(t * 2 + 1) * EE + e];
    atomicOr(&g_bm[t][s * WPR + (g >> 5)], 1u << (g & 31));
    atomicOr(&g_bm[t][g * WPR + (s >> 5)], 1u << (s & 31));
}

// ------------------------------------------------------- initial linear scores
__global__ void k_score0(const float* __restrict__ inputs,
                         const float* __restrict__ lw,
                         const float* __restrict__ lb) {
    int warp = threadIdx.x >> 5, lane = threadIdx.x & 31;
    int row  = blockIdx.x * (blockDim.x >> 5) + warp;
    float acc = 0.0f;
    #pragma unroll
    for (int c = lane; c < ATT_DIM; c += 32)
        acc += inputs[row * ATT_DIM + c] * lw[c];
    #pragma unroll
    for (int o = 16; o; o >>= 1) acc += __shfl_xor_sync(0xFFFFFFFFu, acc, o);
    if (lane == 0) g_s0[row] = acc + lb[0];
}

// ----------------------------------------------- deterministic sum of scores
__global__ void k_reduce(int which) {
    const float* s = which ? g_s1 : g_s0;
    __shared__ float sh[1024];
    int t = threadIdx.x;
    sh[t] = s[t] + s[t + 1024] + s[t + 2048] + s[t + 3072];
    __syncthreads();
    for (int o = 512; o; o >>= 1) {
        if (t < o) sh[t] += sh[t + o];
        __syncthreads();
    }
    if (t == 0) g_S = sh[0];
}

// ----------------------------------- sparse attention pass (both heads fused)
// 128 threads/block = 4 warps, one row per warp, 1024 blocks cover 4096 rows.
__global__ void __launch_bounds__(128) k_pass(int layer, float* __restrict__ out_ext) {
    const float* __restrict__ s = (layer == 0) ? g_s0 : g_s1;
    float* __restrict__ outp    = (layer == 0) ? g_s1 : out_ext;

    __shared__ float ss[NN];        // all 4096 scores (16KB), fast random access
    __shared__ float slut[HEADS][8];

    int tid = threadIdx.x;
    for (int i = tid; i < NN; i += 128) ss[i] = s[i];
    if (tid < HEADS * 8) slut[tid >> 3][tid & 7] = g_lut[layer][tid >> 3][tid & 7];
    __syncthreads();

    int warp = tid >> 5, lane = tid & 31;
    int row  = blockIdx.x * 4 + warp;

    float S   = g_S;
    float a0  = g_a[layer][0], bb0 = g_bb[layer][0];
    float a1  = g_a[layer][1], bb1 = g_bb[layer][1];
    float si  = ss[row];
    float c0  = a0 * si, c1 = a1 * si;

    float e0 = 0.0f, n0 = 0.0f, e1 = 0.0f, n1 = 0.0f;

    const unsigned* __restrict__ b0p = &g_bm[0][row * WPR];
    const unsigned* __restrict__ b1p = &g_bm[1][row * WPR];
    const unsigned* __restrict__ b2p = &g_bm[2][row * WPR];

    #pragma unroll
    for (int c = 0; c < 4; c++) {
        int k = c * 32 + lane;
        unsigned w0 = b0p[k], w1 = b1p[k], w2 = b2p[k];
        unsigned u = w0 | w1 | w2;
        while (u) {
            int b = __ffs(u) - 1;
            u &= u - 1;
            int m = ((w0 >> b) & 1) | (((w1 >> b) & 1) << 1) | (((w2 >> b) & 1) << 2);
            float M  = (float)__popc((unsigned)m);
            float sj = ss[k * 32 + b];

            float x = M * (c0 + bb0 * sj) + slut[0][m];
            x = (x > 0.0f) ? x : NEG * x;
            float v = __expf(x) - 1.0f;
            e0 += v; n0 += v * sj;

            x = M * (c1 + bb1 * sj) + slut[1][m];
            x = (x > 0.0f) ? x : NEG * x;
            v = __expf(x) - 1.0f;
            e1 += v; n1 += v * sj;
        }
    }

    #pragma unroll
    for (int o = 16; o; o >>= 1) {
        e0 += __shfl_xor_sync(0xFFFFFFFFu, e0, o);
        n0 += __shfl_xor_sync(0xFFFFFFFFu, n0, o);
        e1 += __shfl_xor_sync(0xFFFFFFFFu, e1, o);
        n1 += __shfl_xor_sync(0xFFFFFFFFu, n1, o);
    }
    if (lane == 0) {
        float r0 = (S + n0) / ((float)NN + e0);
        float r1 = (S + n1) / ((float)NN + e1);
        outp[row] = 0.5f * (r0 + r1);
    }
}

// ---------------------------------------------------------------- launch
extern "C" void kernel_launch(void* const* d_in, const int* in_sizes, int n_in,
                              void* d_out, int out_size) {
    const float* inputs    = (const float*)d_in[0];
    const float* lin_w     = (const float*)d_in[1];
    const float* lin_b     = (const float*)d_in[2];
    const float* edge_emb  = (const float*)d_in[3];
    const float* att_w     = (const float*)d_in[4];
    const int*   edge_lists= (const int*)  d_in[5];
    float* out = (float*)d_out;

    k_zero   <<<1536, 256>>>();
    k_consts <<<1, 32>>>(edge_emb, att_w);
    k_scatter<<<(TT * EE) / 256, 256>>>(edge_lists);
    k_score0 <<<NN / 8, 256>>>(inputs, lin_w, lin_b);

    k_reduce<<<1, 1024>>>(0);
    k_pass  <<<NN / 4, 128>>>(0, out);
    k_reduce<<<1, 1024>>>(1);
    k_pass  <<<NN / 4, 128>>>(1, out);
}

// round 2
// speedup vs baseline: 1.2640x; 1.2640x over previous
#include <cuda_runtime.h>

#define NN 4096
#define TT 3
#define DD 20
#define EE 131072      // 2^17
#define ATT_DIM 128
#define HEADS 2
#define LAYERS 2
#define WPR 128        // 32-bit words per bitmap row (4096/32)
#define NEG 0.2f
#define MAXDEG 384     // expected degree ~192, sigma ~14 -> 13.8 sigma headroom
#define L2E 1.4426950408889634f

// ---- device scratch (static, allocation-free) ----
__device__ unsigned       g_bm[TT][NN * WPR];     // 3 x 2MB adjacency bitmaps
__device__ unsigned short g_ent[NN * MAXDEG];     // packed CSR: j | (m<<12)
__device__ int            g_cnt[NN];
__device__ float          g_s0[NN];
__device__ float          g_s1[NN];

__device__ __forceinline__ float ex2f(float x) {
    float r;
    asm("ex2.approx.ftz.f32 %0, %1;" : "=f"(r) : "f"(x));
    return r;
}

// ---------------------------------------------------------------- zero bitmaps
__global__ void k_zero() {
    uint4* p = reinterpret_cast<uint4*>(&g_bm[0][0]);
    int i = blockIdx.x * blockDim.x + threadIdx.x;  // 1536*256 covers 393216 uint4
    p[i] = make_uint4(0u, 0u, 0u, 0u);
}

// ---------------------------------------------------------------- edge scatter
__global__ void k_scatter(const int* __restrict__ el) {
    int i = blockIdx.x * blockDim.x + threadIdx.x;   // i < TT*EE
    int t = i >> 17;               // EE = 2^17
    int e = i & (EE - 1);
    int s = el[(t * 2 + 0) * EE + e];
    int g = el[(t * 2 + 1) * EE + e];
    atomicOr(&g_bm[t][s * WPR + (g >> 5)], 1u << (g & 31));
    atomicOr(&g_bm[t][g * WPR + (s >> 5)], 1u << (s & 31));
}

// ------------------------------------------------------- initial linear scores
// warp per row, one LDG.128 per lane
__global__ void k_score0(const float* __restrict__ inputs,
                         const float* __restrict__ lw,
                         const float* __restrict__ lb) {
    int warp = threadIdx.x >> 5, lane = threadIdx.x & 31;
    int row  = blockIdx.x * 8 + warp;      // 256 threads = 8 warps, 512 blocks
    float4 v = reinterpret_cast<const float4*>(inputs + row * ATT_DIM)[lane];
    float4 w = reinterpret_cast<const float4*>(lw)[lane];
    float acc = v.x * w.x + v.y * w.y + v.z * w.z + v.w * w.w;
    #pragma unroll
    for (int o = 16; o; o >>= 1) acc += __shfl_xor_sync(0xFFFFFFFFu, acc, o);
    if (lane == 0) g_s0[row] = acc + lb[0];
}

// ------------------------------------------------- bitmap -> packed CSR (once)
// warp per row; warp-scan assigns compact positions.
__global__ void __launch_bounds__(128) k_build() {
    int warp = threadIdx.x >> 5, lane = threadIdx.x & 31;
    int row  = blockIdx.x * 4 + warp;

    const unsigned* __restrict__ b0p = &g_bm[0][row * WPR];
    const unsigned* __restrict__ b1p = &g_bm[1][row * WPR];
    const unsigned* __restrict__ b2p = &g_bm[2][row * WPR];
    unsigned short* __restrict__ out = &g_ent[row * MAXDEG];

    int total = 0;
    #pragma unroll
    for (int c = 0; c < 4; c++) {
        int k = c * 32 + lane;
        unsigned w0 = b0p[k], w1 = b1p[k], w2 = b2p[k];
        unsigned u = w0 | w1 | w2;
        int cnt = __popc(u);
        // inclusive warp scan of cnt
        int inc = cnt;
        #pragma unroll
        for (int o = 1; o < 32; o <<= 1) {
            int n = __shfl_up_sync(0xFFFFFFFFu, inc, o);
            if (lane >= o) inc += n;
        }
        int base = total + inc - cnt;
        total += __shfl_sync(0xFFFFFFFFu, inc, 31);
        while (u) {
            int b = __ffs(u) - 1;
            u &= u - 1;
            int m = ((w0 >> b) & 1) | (((w1 >> b) & 1) << 1) | (((w2 >> b) & 1) << 2);
            out[base++] = (unsigned short)((k * 32 + b) | (m << 12));
        }
    }
    if (lane == 0) g_cnt[row] = total;
}

// ---------------------------------------------- fused attention pass (1 layer)
// 512 threads = 16 warps = 16 rows/block, 256 blocks.
// Prologue: stage scores to shared + block-reduce S + compute head constants.
__global__ void __launch_bounds__(512) k_pass(int layer,
                                              const float* __restrict__ edge_emb,
                                              const float* __restrict__ att_w,
                                              float* __restrict__ out_ext) {
    const float* __restrict__ s = (layer == 0) ? g_s0 : g_s1;
    float* __restrict__ outp    = (layer == 0) ? g_s1 : out_ext;

    __shared__ float  ss[NN];          // 16KB: all scores
    __shared__ float4 tab4[8];         // per-mask: (lut0', lut1', M, 0)
    __shared__ float  sh_ab[4];        // a0', b0', a1', b1'  (log2e folded)
    __shared__ float  red[16];
    __shared__ float  shS;

    int tid = threadIdx.x;
    int warp = tid >> 5, lane = tid & 31;

    // stage scores + partial sum
    float part = 0.0f;
    #pragma unroll
    for (int i = tid; i < NN; i += 512) { float v = s[i]; ss[i] = v; part += v; }
    #pragma unroll
    for (int o = 16; o; o >>= 1) part += __shfl_xor_sync(0xFFFFFFFFu, part, o);
    if (lane == 0) red[warp] = part;

    // head constants (threads 0,1 -> heads; thread 2 -> M column)
    float* tabf = reinterpret_cast<float*>(tab4);
    if (tid < HEADS) {
        int h = tid;
        const float* w = att_w + (layer * HEADS + h) * (DD + 2);
        float et[TT];
        #pragma unroll
        for (int t = 0; t < TT; t++) {
            float acc = 0.0f;
            #pragma unroll
            for (int d = 0; d < DD; d++) acc += edge_emb[t * DD + d] * w[1 + d];
            et[t] = acc * L2E;
        }
        sh_ab[h * 2 + 0] = w[0] * L2E;
        sh_ab[h * 2 + 1] = w[DD + 1] * L2E;
        #pragma unroll
        for (int m = 0; m < 8; m++) {
            float B = 0.0f;
            #pragma unroll
            for (int t = 0; t < TT; t++) if ((m >> t) & 1) B += et[t];
            tabf[m * 4 + h] = B;
        }
    } else if (tid == 2) {
        #pragma unroll
        for (int m = 0; m < 8; m++) tabf[m * 4 + 2] = (float)__popc((unsigned)m);
    }
    __syncthreads();

    if (tid < 32) {  // final S reduce
        float v = (tid < 16) ? red[tid] : 0.0f;
        #pragma unroll
        for (int o = 8; o; o >>= 1) v += __shfl_xor_sync(0xFFFFFFFFu, v, o);
        if (tid == 0) shS = v;
    }
    __syncthreads();

    int row = blockIdx.x * 16 + warp;
    float S  = shS;
    float si = ss[row];
    float a0 = sh_ab[0], b0 = sh_ab[1], a1 = sh_ab[2], b1 = sh_ab[3];
    float c0 = a0 * si, c1 = a1 * si;

    int cnt = g_cnt[row];
    const unsigned short* __restrict__ ep = &g_ent[row * MAXDEG];

    float e0 = 0.0f, n0 = 0.0f, e1 = 0.0f, n1 = 0.0f, sjs = 0.0f;

    for (int k = lane; k < cnt; k += 32) {
        int e = ep[k];
        int j = e & 0xFFF;
        int m = e >> 12;
        float4 t4 = tab4[m];          // (lut0', lut1', M, _)
        float sj = ss[j];
        float M  = t4.z;

        float x0 = fmaf(M, fmaf(b0, sj, c0), t4.x);
        x0 = fmaxf(x0, NEG * x0);     // lrelu (log2-scaled, scale>0 commutes)
        float v0 = ex2f(x0);
        e0 += v0; n0 = fmaf(v0, sj, n0);

        float x1 = fmaf(M, fmaf(b1, sj, c1), t4.y);
        x1 = fmaxf(x1, NEG * x1);
        float v1 = ex2f(x1);
        e1 += v1; n1 = fmaf(v1, sj, n1);

        sjs += sj;
    }

    #pragma unroll
    for (int o = 16; o; o >>= 1) {
        e0  += __shfl_xor_sync(0xFFFFFFFFu, e0,  o);
        n0  += __shfl_xor_sync(0xFFFFFFFFu, n0,  o);
        e1  += __shfl_xor_sync(0xFFFFFFFFu, e1,  o);
        n1  += __shfl_xor_sync(0xFFFFFFFFu, n1,  o);
        sjs += __shfl_xor_sync(0xFFFFFFFFu, sjs, o);
    }
    if (lane == 0) {
        // v_true = e^x - 1 accumulated as (sum e^x) - cnt ; similarly for numer
        float fc = (float)cnt;
        float r0 = (S + n0 - sjs) / ((float)NN + e0 - fc);
        float r1 = (S + n1 - sjs) / ((float)NN + e1 - fc);
        outp[row] = 0.5f * (r0 + r1);
    }
}

// ---------------------------------------------------------------- launch
extern "C" void kernel_launch(void* const* d_in, const int* in_sizes, int n_in,
                              void* d_out, int out_size) {
    const float* inputs     = (const float*)d_in[0];
    const float* lin_w      = (const float*)d_in[1];
    const float* lin_b      = (const float*)d_in[2];
    const float* edge_emb   = (const float*)d_in[3];
    const float* att_w      = (const float*)d_in[4];
    const int*   edge_lists = (const int*)  d_in[5];
    float* out = (float*)d_out;

    k_zero   <<<1536, 256>>>();
    k_scatter<<<(TT * EE) / 256, 256>>>(edge_lists);
    k_score0 <<<NN / 8, 256>>>(inputs, lin_w, lin_b);
    k_build  <<<NN / 4, 128>>>();
    k_pass   <<<NN / 16, 512>>>(0, edge_emb, att_w, out);
    k_pass   <<<NN / 16, 512>>>(1, edge_emb, att_w, out);
}

// round 3
// speedup vs baseline: 1.2693x; 1.0042x over previous
#include <cuda_runtime.h>

#define NN 4096
#define TT 3
#define DD 20
#define EE 131072      // 2^17
#define ATT_DIM 128
#define HEADS 2
#define LAYERS 2
#define WPR 128        // 32-bit words per bitmap row (4096/32)
#define NEG 0.2f
#define MAXDEG 384     // mean degree ~192, sigma ~14 -> huge headroom
#define L2E 1.4426950408889634f
#define NBLK 256       // mega-kernel grid (must be <= resident capacity)

// ---- device scratch (static, allocation-free) ----
// interleaved bitmaps: word layout [row][word][4] (lane 3 = pad) -> one LDG.128
__device__ unsigned       g_bmi[NN * WPR * 4];    // 8MB
__device__ unsigned short g_ent[NN * MAXDEG];     // packed CSR: j | (m<<12)
__device__ int            g_cnt[NN];              // padded-to-even counts
__device__ float          g_s0[NN];
__device__ float          g_s1[NN];
__device__ unsigned       g_bar_cnt = 0;
__device__ volatile unsigned g_bar_gen = 0;

__device__ __forceinline__ float ex2f(float x) {
    float r;
    asm("ex2.approx.ftz.f32 %0, %1;" : "=f"(r) : "f"(x));
    return r;
}

// all-resident grid barrier (generation-based; safe across graph replays)
__device__ __forceinline__ void grid_barrier() {
    __syncthreads();
    if (threadIdx.x == 0) {
        __threadfence();
        unsigned gen = g_bar_gen;
        unsigned t = atomicAdd(&g_bar_cnt, 1u);
        if (t == (unsigned)(gridDim.x - 1)) {
            g_bar_cnt = 0;
            __threadfence();
            g_bar_gen = gen + 1u;
        } else {
            while (g_bar_gen == gen) { }
        }
    }
    __syncthreads();
}

// ---------------------------------------------------------------- zero bitmaps
__global__ void k_zero() {
    uint4* p = reinterpret_cast<uint4*>(&g_bmi[0]);
    int i = blockIdx.x * blockDim.x + threadIdx.x;  // 2048*256 = 524288 uint4
    p[i] = make_uint4(0u, 0u, 0u, 0u);
}

// ---------------------------------------------------------------- edge scatter
__global__ void k_scatter(const int* __restrict__ el) {
    int i = blockIdx.x * blockDim.x + threadIdx.x;   // i < TT*EE
    int t = i >> 17;               // EE = 2^17
    int e = i & (EE - 1);
    int s = el[(t * 2 + 0) * EE + e];
    int g = el[(t * 2 + 1) * EE + e];
    atomicOr(&g_bmi[(s * WPR + (g >> 5)) * 4 + t], 1u << (g & 31));
    atomicOr(&g_bmi[(g * WPR + (s >> 5)) * 4 + t], 1u << (s & 31));
}

// ------------------------------------------------- bitmap -> packed CSR (once)
// one block per row, one 32-bit word per thread; warp scan + cross-warp prefix
__global__ void __launch_bounds__(128) k_build() {
    __shared__ int wsum[4];
    int row  = blockIdx.x;
    int warp = threadIdx.x >> 5, lane = threadIdx.x & 31;
    int k    = threadIdx.x;                 // word index 0..127

    uint4 w = reinterpret_cast<const uint4*>(&g_bmi[0])[row * WPR + k];
    unsigned w0 = w.x, w1 = w.y, w2 = w.z;
    unsigned u  = w0 | w1 | w2;
    int cnt = __popc(u);

    int inc = cnt;                          // inclusive warp scan
    #pragma unroll
    for (int o = 1; o < 32; o <<= 1) {
        int n = __shfl_up_sync(0xFFFFFFFFu, inc, o);
        if (lane >= o) inc += n;
    }
    if (lane == 31) wsum[warp] = inc;
    __syncthreads();

    int base = inc - cnt;                   // exclusive within warp
    #pragma unroll
    for (int ww = 0; ww < 3; ww++) if (ww < warp) base += wsum[ww];

    unsigned short* __restrict__ outp = &g_ent[row * MAXDEG];
    int col = k * 32;
    while (u) {
        int b = __ffs(u) - 1;
        u &= u - 1;
        int m = ((w0 >> b) & 1) | (((w1 >> b) & 1) << 1) | (((w2 >> b) & 1) << 2);
        outp[base++] = (unsigned short)((col + b) | (m << 12));
    }

    if (threadIdx.x == 127) {               // warp3 lane31: inc == warp3 total
        int tot = wsum[0] + wsum[1] + wsum[2] + inc;
        if (tot & 1) { outp[tot] = 0; tot++; }   // pad: (j=0,m=0) is exact no-op
        g_cnt[row] = tot;
    }
}

// --------------------------------- fused score0 + layer0 + layer1 (persistent)
// 256 blocks x 512 threads, all-resident; one row per warp (256*16 = 4096)
__global__ void __launch_bounds__(512) k_mega(const float* __restrict__ inputs,
                                              const float* __restrict__ lw,
                                              const float* __restrict__ lb,
                                              const float* __restrict__ edge_emb,
                                              const float* __restrict__ att_w,
                                              float* __restrict__ out) {
    __shared__ float  ss[NN];          // 16KB: all scores
    __shared__ float4 tab4[8];         // per-mask: (lut0', lut1', M, _)
    __shared__ float  sh_ab[4];        // a0', b0', a1', b1'  (log2e folded)
    __shared__ float  red[16];
    __shared__ float  shS;

    int tid  = threadIdx.x;
    int warp = tid >> 5, lane = tid & 31;
    int row  = blockIdx.x * 16 + warp;

    // ---- phase 0: initial linear score, one row per warp
    {
        float4 v = reinterpret_cast<const float4*>(inputs + row * ATT_DIM)[lane];
        float4 w = reinterpret_cast<const float4*>(lw)[lane];
        float acc = v.x * w.x + v.y * w.y + v.z * w.z + v.w * w.w;
        #pragma unroll
        for (int o = 16; o; o >>= 1) acc += __shfl_xor_sync(0xFFFFFFFFu, acc, o);
        if (lane == 0) g_s0[row] = acc + lb[0];
    }
    int cnt = g_cnt[row];
    const unsigned* __restrict__ ep32 =
        reinterpret_cast<const unsigned*>(&g_ent[row * MAXDEG]);

    grid_barrier();

    float* tabf = reinterpret_cast<float*>(tab4);

    #pragma unroll 1
    for (int layer = 0; layer < LAYERS; layer++) {
        const float* __restrict__ sp = (layer == 0) ? g_s0 : g_s1;

        // stage scores (L2 path: cross-SM freshness) + partial sum
        float part = 0.0f;
        #pragma unroll
        for (int i = tid; i < NN; i += 512) {
            float v = __ldcg(sp + i);
            ss[i] = v; part += v;
        }
        #pragma unroll
        for (int o = 16; o; o >>= 1) part += __shfl_xor_sync(0xFFFFFFFFu, part, o);
        if (lane == 0) red[warp] = part;

        // head constants
        if (tid < HEADS) {
            int h = tid;
            const float* w = att_w + (layer * HEADS + h) * (DD + 2);
            float et[TT];
            #pragma unroll
            for (int t = 0; t < TT; t++) {
                float acc = 0.0f;
                #pragma unroll
                for (int d = 0; d < DD; d++) acc += edge_emb[t * DD + d] * w[1 + d];
                et[t] = acc * L2E;
            }
            sh_ab[h * 2 + 0] = w[0] * L2E;
            sh_ab[h * 2 + 1] = w[DD + 1] * L2E;
            #pragma unroll
            for (int m = 0; m < 8; m++) {
                float B = 0.0f;
                #pragma unroll
                for (int t = 0; t < TT; t++) if ((m >> t) & 1) B += et[t];
                tabf[m * 4 + h] = B;
            }
        } else if (tid == 2) {
            #pragma unroll
            for (int m = 0; m < 8; m++) tabf[m * 4 + 2] = (float)__popc((unsigned)m);
        }
        __syncthreads();

        if (tid < 32) {  // final S reduce
            float v = (tid < 16) ? red[tid] : 0.0f;
            #pragma unroll
            for (int o = 8; o; o >>= 1) v += __shfl_xor_sync(0xFFFFFFFFu, v, o);
            if (tid == 0) shS = v;
        }
        __syncthreads();

        float S  = shS;
        float si = ss[row];
        float a0 = sh_ab[0], b0 = sh_ab[1], a1 = sh_ab[2], b1 = sh_ab[3];
        float c0 = a0 * si, c1 = a1 * si;

        float e0 = 0.0f, n0 = 0.0f, e1 = 0.0f, n1 = 0.0f, sjs = 0.0f;

        for (int k = lane; 2 * k < cnt; k += 32) {
            unsigned pr = ep32[k];
            #pragma unroll
            for (int half = 0; half < 2; half++) {
                int e = (half == 0) ? (pr & 0xFFFFu) : (pr >> 16);
                int j = e & 0xFFF;
                int m = e >> 12;
                float4 t4 = tab4[m];          // (lut0', lut1', M, _)
                float sj = ss[j];
                float M  = t4.z;

                float x0 = fmaf(M, fmaf(b0, sj, c0), t4.x);
                x0 = fmaxf(x0, NEG * x0);
                float v0 = ex2f(x0);
                e0 += v0; n0 = fmaf(v0, sj, n0);

                float x1 = fmaf(M, fmaf(b1, sj, c1), t4.y);
                x1 = fmaxf(x1, NEG * x1);
                float v1 = ex2f(x1);
                e1 += v1; n1 = fmaf(v1, sj, n1);

                sjs += sj;
            }
        }

        #pragma unroll
        for (int o = 16; o; o >>= 1) {
            e0  += __shfl_xor_sync(0xFFFFFFFFu, e0,  o);
            n0  += __shfl_xor_sync(0xFFFFFFFFu, n0,  o);
            e1  += __shfl_xor_sync(0xFFFFFFFFu, e1,  o);
            n1  += __shfl_xor_sync(0xFFFFFFFFu, n1,  o);
            sjs += __shfl_xor_sync(0xFFFFFFFFu, sjs, o);
        }
        if (lane == 0) {
            float fc = (float)cnt;
            float r0 = (S + n0 - sjs) / ((float)NN + e0 - fc);
            float r1 = (S + n1 - sjs) / ((float)NN + e1 - fc);
            float r  = 0.5f * (r0 + r1);
            if (layer == 0) g_s1[row] = r;
            else            out[row]  = r;
        }

        if (layer == 0) grid_barrier();
    }
}

// ---------------------------------------------------------------- launch
extern "C" void kernel_launch(void* const* d_in, const int* in_sizes, int n_in,
                              void* d_out, int out_size) {
    const float* inputs     = (const float*)d_in[0];
    const float* lin_w      = (const float*)d_in[1];
    const float* lin_b      = (const float*)d_in[2];
    const float* edge_emb   = (const float*)d_in[3];
    const float* att_w      = (const float*)d_in[4];
    const int*   edge_lists = (const int*)  d_in[5];
    float* out = (float*)d_out;

    k_zero   <<<2048, 256>>>();
    k_scatter<<<(TT * EE) / 256, 256>>>(edge_lists);
    k_build  <<<NN, 128>>>();
    k_mega   <<<NBLK, 512>>>(inputs, lin_w, lin_b, edge_emb, att_w, out);
}

// round 4
// speedup vs baseline: 1.2841x; 1.0116x over previous
#include <cuda_runtime.h>

#define NN 4096
#define TT 3
#define DD 20
#define EE 131072      // 2^17
#define ATT_DIM 128
#define HEADS 2
#define LAYERS 2
#define WPR 128        // 32-bit words per bitmap row (4096/32)
#define NEG 0.2f
#define MAXDEG 384     // mean degree ~192, sigma ~14 -> huge headroom
#define L2E 1.4426950408889634f
#define NBLK 256       // mega-kernel grid (must be <= resident capacity)

// ---- device scratch (static, allocation-free) ----
// interleaved bitmaps: word layout [row][word][4] (lane 3 = pad) -> one LDG.128
__device__ unsigned       g_bmi[NN * WPR * 4];    // 8MB
__device__ unsigned short g_ent[NN * MAXDEG];     // packed CSR: j | (m<<12)
__device__ int            g_cnt[NN];              // padded-to-even counts
__device__ float          g_s0[NN];
__device__ float          g_s1[NN];
__device__ unsigned       g_bar_cnt = 0;
__device__ volatile unsigned g_bar_gen = 0;

__device__ __forceinline__ float ex2f(float x) {
    float r;
    asm("ex2.approx.ftz.f32 %0, %1;" : "=f"(r) : "f"(x));
    return r;
}

// all-resident grid barrier (generation-based; safe across graph replays)
__device__ __forceinline__ void grid_barrier() {
    __syncthreads();
    if (threadIdx.x == 0) {
        __threadfence();
        unsigned gen = g_bar_gen;
        unsigned t = atomicAdd(&g_bar_cnt, 1u);
        if (t == (unsigned)(gridDim.x - 1)) {
            g_bar_cnt = 0;
            __threadfence();
            g_bar_gen = gen + 1u;
        } else {
            while (g_bar_gen == gen) { }
        }
    }
    __syncthreads();
}

// ---------------------------------------------------------------- zero bitmaps
__global__ void k_zero() {
    uint4* p = reinterpret_cast<uint4*>(&g_bmi[0]);
    int i = blockIdx.x * blockDim.x + threadIdx.x;  // 2048*256 = 524288 uint4
    p[i] = make_uint4(0u, 0u, 0u, 0u);
}

// ---------------------------------------------------------------- edge scatter
__global__ void k_scatter(const int* __restrict__ el) {
    int i = blockIdx.x * blockDim.x + threadIdx.x;   // i < TT*EE
    int t = i >> 17;               // EE = 2^17
    int e = i & (EE - 1);
    int s = el[(t * 2 + 0) * EE + e];
    int g = el[(t * 2 + 1) * EE + e];
    atomicOr(&g_bmi[(s * WPR + (g >> 5)) * 4 + t], 1u << (g & 31));
    atomicOr(&g_bmi[(g * WPR + (s >> 5)) * 4 + t], 1u << (s & 31));
}

// ------------------------------------------------- bitmap -> packed CSR (once)
// one block per row, one 32-bit word per thread; warp scan + cross-warp prefix
__global__ void __launch_bounds__(128) k_build() {
    __shared__ int wsum[4];
    int row  = blockIdx.x;
    int warp = threadIdx.x >> 5, lane = threadIdx.x & 31;
    int k    = threadIdx.x;                 // word index 0..127

    uint4 w = reinterpret_cast<const uint4*>(&g_bmi[0])[row * WPR + k];
    unsigned w0 = w.x, w1 = w.y, w2 = w.z;
    unsigned u  = w0 | w1 | w2;
    int cnt = __popc(u);

    int inc = cnt;                          // inclusive warp scan
    #pragma unroll
    for (int o = 1; o < 32; o <<= 1) {
        int n = __shfl_up_sync(0xFFFFFFFFu, inc, o);
        if (lane >= o) inc += n;
    }
    if (lane == 31) wsum[warp] = inc;
    __syncthreads();

    int base = inc - cnt;                   // exclusive within warp
    #pragma unroll
    for (int ww = 0; ww < 3; ww++) if (ww < warp) base += wsum[ww];

    unsigned short* __restrict__ outp = &g_ent[row * MAXDEG];
    int col = k * 32;
    while (u) {
        int b = __ffs(u) - 1;
        u &= u - 1;
        int m = ((w0 >> b) & 1) | (((w1 >> b) & 1) << 1) | (((w2 >> b) & 1) << 2);
        outp[base++] = (unsigned short)((col + b) | (m << 12));
    }

    if (threadIdx.x == 127) {               // warp3 lane31: inc == warp3 total
        int tot = wsum[0] + wsum[1] + wsum[2] + inc;
        if (tot & 1) { outp[tot] = 0; tot++; }   // pad: (j=0,m=0) is exact no-op
        g_cnt[row] = tot;
    }
}

// --------------------------------- fused score0 + layer0 + layer1 (persistent)
// 256 blocks x 512 threads, all-resident; one row per warp (256*16 = 4096)
__global__ void __launch_bounds__(512) k_mega(const float* __restrict__ inputs,
                                              const float* __restrict__ lw,
                                              const float* __restrict__ lb,
                                              const float* __restrict__ edge_emb,
                                              const float* __restrict__ att_w,
                                              float* __restrict__ out) {
    __shared__ float  ss[NN];          // 16KB: all scores
    __shared__ float4 tab4[8];         // per-mask: (lut0', lut1', M, _)
    __shared__ float  sh_ab[4];        // a0', b0', a1', b1'  (log2e folded)
    __shared__ float  red[16];
    __shared__ float  shS;

    int tid  = threadIdx.x;
    int warp = tid >> 5, lane = tid & 31;
    int row  = blockIdx.x * 16 + warp;

    // ---- phase 0: initial linear score, one row per warp
    {
        float4 v = reinterpret_cast<const float4*>(inputs + row * ATT_DIM)[lane];
        float4 w = reinterpret_cast<const float4*>(lw)[lane];
        float acc = v.x * w.x + v.y * w.y + v.z * w.z + v.w * w.w;
        #pragma unroll
        for (int o = 16; o; o >>= 1) acc += __shfl_xor_sync(0xFFFFFFFFu, acc, o);
        if (lane == 0) g_s0[row] = acc + lb[0];
    }
    int cnt = g_cnt[row];
    const unsigned* __restrict__ ep32 =
        reinterpret_cast<const unsigned*>(&g_ent[row * MAXDEG]);

    grid_barrier();

    float* tabf = reinterpret_cast<float*>(tab4);

    #pragma unroll 1
    for (int layer = 0; layer < LAYERS; layer++) {
        const float* __restrict__ sp = (layer == 0) ? g_s0 : g_s1;

        // stage scores (L2 path: cross-SM freshness) + partial sum
        float part = 0.0f;
        #pragma unroll
        for (int i = tid; i < NN; i += 512) {
            float v = __ldcg(sp + i);
            ss[i] = v; part += v;
        }
        #pragma unroll
        for (int o = 16; o; o >>= 1) part += __shfl_xor_sync(0xFFFFFFFFu, part, o);
        if (lane == 0) red[warp] = part;

        // head constants
        if (tid < HEADS) {
            int h = tid;
            const float* w = att_w + (layer * HEADS + h) * (DD + 2);
            float et[TT];
            #pragma unroll
            for (int t = 0; t < TT; t++) {
                float acc = 0.0f;
                #pragma unroll
                for (int d = 0; d < DD; d++) acc += edge_emb[t * DD + d] * w[1 + d];
                et[t] = acc * L2E;
            }
            sh_ab[h * 2 + 0] = w[0] * L2E;
            sh_ab[h * 2 + 1] = w[DD + 1] * L2E;
            #pragma unroll
            for (int m = 0; m < 8; m++) {
                float B = 0.0f;
                #pragma unroll
                for (int t = 0; t < TT; t++) if ((m >> t) & 1) B += et[t];
                tabf[m * 4 + h] = B;
            }
        } else if (tid == 2) {
            #pragma unroll
            for (int m = 0; m < 8; m++) tabf[m * 4 + 2] = (float)__popc((unsigned)m);
        }
        __syncthreads();

        if (tid < 32) {  // final S reduce
            float v = (tid < 16) ? red[tid] : 0.0f;
            #pragma unroll
            for (int o = 8; o; o >>= 1) v += __shfl_xor_sync(0xFFFFFFFFu, v, o);
            if (tid == 0) shS = v;
        }
        __syncthreads();

        float S  = shS;
        float si = ss[row];
        float a0 = sh_ab[0], b0 = sh_ab[1], a1 = sh_ab[2], b1 = sh_ab[3];
        float c0 = a0 * si, c1 = a1 * si;

        float e0 = 0.0f, n0 = 0.0f, e1 = 0.0f, n1 = 0.0f, sjs = 0.0f;

        for (int k = lane; 2 * k < cnt; k += 32) {
            unsigned pr = ep32[k];
            #pragma unroll
            for (int half = 0; half < 2; half++) {
                int e = (half == 0) ? (pr & 0xFFFFu) : (pr >> 16);
                int j = e & 0xFFF;
                int m = e >> 12;
                float4 t4 = tab4[m];          // (lut0', lut1', M, _)
                float sj = ss[j];
                float M  = t4.z;

                float x0 = fmaf(M, fmaf(b0, sj, c0), t4.x);
                x0 = fmaxf(x0, NEG * x0);
                float v0 = ex2f(x0);
                e0 += v0; n0 = fmaf(v0, sj, n0);

                float x1 = fmaf(M, fmaf(b1, sj, c1), t4.y);
                x1 = fmaxf(x1, NEG * x1);
                float v1 = ex2f(x1);
                e1 += v1; n1 = fmaf(v1, sj, n1);

                sjs += sj;
            }
        }

        #pragma unroll
        for (int o = 16; o; o >>= 1) {
            e0  += __shfl_xor_sync(0xFFFFFFFFu, e0,  o);
            n0  += __shfl_xor_sync(0xFFFFFFFFu, n0,  o);
            e1  += __shfl_xor_sync(0xFFFFFFFFu, e1,  o);
            n1  += __shfl_xor_sync(0xFFFFFFFFu, n1,  o);
            sjs += __shfl_xor_sync(0xFFFFFFFFu, sjs, o);
        }
        if (lane == 0) {
            float fc = (float)cnt;
            float r0 = (S + n0 - sjs) / ((float)NN + e0 - fc);
            float r1 = (S + n1 - sjs) / ((float)NN + e1 - fc);
            float r  = 0.5f * (r0 + r1);
            if (layer == 0) g_s1[row] = r;
            else            out[row]  = r;
        }

        if (layer == 0) grid_barrier();
    }
}

// ---------------------------------------------------------------- launch
extern "C" void kernel_launch(void* const* d_in, const int* in_sizes, int n_in,
                              void* d_out, int out_size) {
    const float* inputs     = (const float*)d_in[0];
    const float* lin_w      = (const float*)d_in[1];
    const float* lin_b      = (const float*)d_in[2];
    const float* edge_emb   = (const float*)d_in[3];
    const float* att_w      = (const float*)d_in[4];
    const int*   edge_lists = (const int*)  d_in[5];
    float* out = (float*)d_out;

    k_zero   <<<2048, 256>>>();
    k_scatter<<<(TT * EE) / 256, 256>>>(edge_lists);
    k_build  <<<NN, 128>>>();
    k_mega   <<<NBLK, 512>>>(inputs, lin_w, lin_b, edge_emb, att_w, out);
}